// round 3
// baseline (speedup 1.0000x reference)
#include <cuda_runtime.h>
#include <math.h>
#include <stdint.h>

#define NN 32768
#define KK 16

// ---------------- scratch (static device globals; no allocation) -------------
__device__ float g_P1 [NN * 256];   // layer1 gate preacts, gate-interleaved [n][d*4+g]
__device__ float g_HN1[NN * 64];    // layer1 LSTM output (final step)
__device__ float g_H1 [NN * 128];   // layer1 SAGE output
__device__ float g_P2 [NN * 512];   // layer2 gate preacts, gate-interleaved
__device__ float g_HN2[NN * 128];   // layer2 LSTM output (final step)
__device__ float g_H2 [NN * 128];   // layer2 SAGE output
__device__ float g_Bp1[64 * 256];   // Whh1 packed tf32, mma-fragment order
__device__ float g_Bp2[128 * 512];  // Whh2 packed tf32, mma-fragment order
__device__ float g_C1 [NN * 64];    // layer1 cell state
__device__ float g_C2 [NN * 128];   // layer2 cell state
__device__ float g_HA1[NN * 64];    // layer1 h ping
__device__ float g_HB1[NN * 64];    // layer1 h pong
__device__ float g_HA2[NN * 128];   // layer2 h ping
__device__ float g_HB2[NN * 128];   // layer2 h pong

__device__ __forceinline__ float sigmoidf_(float x) { return 1.0f / (1.0f + __expf(-x)); }

__device__ __forceinline__ uint32_t f2tf32(float v) {
    uint32_t u;
    asm("cvt.rna.tf32.f32 %0, %1;" : "=r"(u) : "f"(v));
    return u;
}

__device__ __forceinline__ void mma_tf32(float* c, const uint32_t* a, const uint32_t* b) {
    asm volatile(
        "mma.sync.aligned.m16n8k8.row.col.f32.tf32.tf32.f32 "
        "{%0,%1,%2,%3}, {%4,%5,%6,%7}, {%8,%9}, {%0,%1,%2,%3};"
        : "+f"(c[0]), "+f"(c[1]), "+f"(c[2]), "+f"(c[3])
        : "r"(a[0]), "r"(a[1]), "r"(a[2]), "r"(a[3]), "r"(b[0]), "r"(b[1]));
}

// -------- pack Whh [f][g*D+d] -> tf32 fragment-ordered Bp --------------------
// Bp layout: idx = ((((cy*K8 + k8)*4 + wc)*2 + p)*128) + lane*4 + q
//   value = Whh[f][g*D+d] where f = k8*8 + (lane&3) + 4*(q&1),
//   ci = cy*128 + wc*32 + (p*2 + (q>>1))*8 + (lane>>2), d = ci>>2, g = ci&3.
__global__ void pack_B(const float* __restrict__ W, float* __restrict__ Bp, int D, int K8)
{
    int idx = blockIdx.x * blockDim.x + threadIdx.x;
    if (idx >= D * 4 * D) return;
    int tmp = idx;
    int q    = tmp & 3;  tmp >>= 2;
    int lane = tmp & 31; tmp >>= 5;
    int p    = tmp & 1;  tmp >>= 1;
    int wc   = tmp & 3;  tmp >>= 2;
    int k8   = tmp % K8;
    int cy   = tmp / K8;
    int f  = k8 * 8 + (lane & 3) + 4 * (q & 1);
    int ci = cy * 128 + wc * 32 + (p * 2 + (q >> 1)) * 8 + (lane >> 2);
    int d = ci >> 2, g = ci & 3;
    uint32_t u = f2tf32(W[f * 4 * D + g * D + d]);
    ((uint32_t*)Bp)[idx] = u;
}

// -------- per-step LSTM: tf32 tensor-core GEMM + fused gather + cell update --
// grid (NN/128, 4*DIM/128), 256 threads (8 warps as 2x4 of 64x32 warp tiles).
template <int DIM>
__global__ void __launch_bounds__(256, 1) lstm_step(
    const float* __restrict__ P,     // [NN][4*DIM] gate-interleaved preacts
    const float* __restrict__ Bp,    // packed tf32 Whh
    const int*   __restrict__ nbr,   // [NN][16]
    const float* __restrict__ Hprev, // [NN][DIM] (unused at t==0)
    float*       __restrict__ Hout,  // [NN][DIM]
    float*       __restrict__ C,     // [NN][DIM] cell state
    int t)
{
    constexpr int K8 = DIM / 8;
    extern __shared__ float smem[];
    uint32_t* Af  = (uint32_t*)smem;            // DIM*128 tf32 A fragments
    float*    Bsm = smem + DIM * 128;           // DIM*128 packed B

    const int tid  = threadIdx.x;
    const int lane = tid & 31;
    const int warp = tid >> 5;
    const int wr   = warp >> 2;    // 0..1  (64-row slabs)
    const int wc   = warp & 3;     // 0..3  (32-col slabs)
    const int m0   = blockIdx.x * 128;
    const int n0   = blockIdx.y * 128;   // interleaved column offset

    // ---- copy packed B slice (reused across all M-tiles & steps, L2-hot) ----
    {
        const float4* src = (const float4*)(Bp + (size_t)blockIdx.y * DIM * 128);
        float4* dst = (float4*)Bsm;
#pragma unroll
        for (int i = tid; i < DIM * 32; i += 256) dst[i] = src[i];
    }

    float acc[4][4][4];
#pragma unroll
    for (int a = 0; a < 4; a++)
#pragma unroll
        for (int b = 0; b < 4; b++)
#pragma unroll
            for (int cc = 0; cc < 4; cc++) acc[a][b][cc] = 0.0f;

    // ---- stage A = Hprev tile into fragment-ordered swizzled smem ----------
    if (t > 0) {
#pragma unroll
        for (int itr = 0; itr < DIM / 8; itr++) {
            int widx = itr * 8 + warp;           // 0 .. 16*(DIM/16)-1
            int ng  = widx / (DIM / 16);         // node group (8 nodes)
            int fbg = widx % (DIM / 16);         // 4-float4 dim group
            int nb = ng * 8;
            int node_l = nb + (lane >> 2);
            int f4 = fbg * 4 + (lane & 3);
            float4 hv = *(const float4*)&Hprev[(size_t)(m0 + node_l) * DIM + f4 * 4];
            int mt    = (nb >> 4) & 3;
            int ibit2 = (nb >> 3) & 1;
            int wrA   = nb >> 6;
            int lane_w = (node_l & 7) << 2;
            float v[4] = {hv.x, hv.y, hv.z, hv.w};
#pragma unroll
            for (int qq = 0; qq < 4; qq++) {
                int dim  = f4 * 4 + qq;
                int k8   = dim >> 3;
                int jbit = (dim >> 2) & 1;
                int i    = (jbit << 1) | ibit2;
                int s    = (i >> 1) | ((k8 & 1) << 1);
                Af[(((k8 * 2 + wrA) * 4 + mt) << 7) + (i << 5) + ((lane_w | qq) ^ s)] = f2tf32(v[qq]);
            }
        }
    }
    __syncthreads();

    // ---- mainloop: DIM/8 k-steps of m16n8k8 tf32 mma -----------------------
    if (t > 0) {
        const float4* B4 = (const float4*)Bsm;
#pragma unroll
        for (int k8 = 0; k8 < K8; k8++) {
            float4 bl = B4[((k8 * 4 + wc) * 2 + 0) * 32 + lane];
            float4 bh = B4[((k8 * 4 + wc) * 2 + 1) * 32 + lane];
            uint32_t b[4][2] = {
                {__float_as_uint(bl.x), __float_as_uint(bl.y)},
                {__float_as_uint(bl.z), __float_as_uint(bl.w)},
                {__float_as_uint(bh.x), __float_as_uint(bh.y)},
                {__float_as_uint(bh.z), __float_as_uint(bh.w)}};
            uint32_t a[4][4];
#pragma unroll
            for (int mt = 0; mt < 4; mt++)
#pragma unroll
                for (int i = 0; i < 4; i++) {
                    int s = (i >> 1) | ((k8 & 1) << 1);
                    a[mt][i] = Af[(((k8 * 2 + wr) * 4 + mt) << 7) + (i << 5) + (lane ^ s)];
                }
#pragma unroll
            for (int mt = 0; mt < 4; mt++)
#pragma unroll
                for (int nt = 0; nt < 4; nt++)
                    mma_tf32(acc[mt][nt], a[mt], b[nt]);
        }
    }

    // ---- epilogue: gather P, LSTM cell update ------------------------------
    const bool evenp = ((lane & 1) == 0);
#pragma unroll
    for (int mt = 0; mt < 4; mt++) {
        int node = m0 + wr * 64 + mt * 16 + (lane >> 2);
        int j0 = __ldg(&nbr[node * KK + t]);
        int j1 = __ldg(&nbr[(node + 8) * KK + t]);
#pragma unroll
        for (int nt = 0; nt < 4; nt++) {
            int ci = n0 + wc * 32 + nt * 8 + 2 * (lane & 3);
            int d  = ci >> 2;
            float2 p0 = *(const float2*)&P[(size_t)j0 * 4 * DIM + ci];
            float2 p1 = *(const float2*)&P[(size_t)j1 * 4 * DIM + ci];
            float g00 = acc[mt][nt][0] + p0.x;   // node,   col even (i | g)
            float g01 = acc[mt][nt][1] + p0.y;   // node,   col odd  (f | o)
            float g10 = acc[mt][nt][2] + p1.x;   // node+8, col even
            float g11 = acc[mt][nt][3] + p1.y;   // node+8, col odd
            // even lane: (i,f) of dim d; odd lane: (g,o) of dim d
            float x00 = evenp ? sigmoidf_(g00) : tanhf(g00);
            float x01 = sigmoidf_(g01);
            float x10 = evenp ? sigmoidf_(g10) : tanhf(g10);
            float x11 = sigmoidf_(g11);
            float y00 = __shfl_xor_sync(0xffffffffu, x00, 1);   // even gets tanh(g)
            float y10 = __shfl_xor_sync(0xffffffffu, x10, 1);
            float c0 = 0.0f, c1 = 0.0f;
            if (evenp && t > 0) {
                c0 = C[(size_t)node * DIM + d];
                c1 = C[(size_t)(node + 8) * DIM + d];
            }
            float cn0 = x01 * c0 + x00 * y00;   // even: sf*c + si*tg
            float cn1 = x11 * c1 + x10 * y10;
            float tc0 = tanhf(cn0);
            float tc1 = tanhf(cn1);
            float tz0 = __shfl_xor_sync(0xffffffffu, tc0, 1);   // odd gets tanh(c)
            float tz1 = __shfl_xor_sync(0xffffffffu, tc1, 1);
            if (evenp) {
                C[(size_t)node * DIM + d] = cn0;
                C[(size_t)(node + 8) * DIM + d] = cn1;
            } else {
                Hout[(size_t)node * DIM + d] = x01 * tz0;       // so * tanh(c)
                Hout[(size_t)(node + 8) * DIM + d] = x11 * tz1;
            }
        }
    }
}

// -------- generic fused SIMT GEMM: C = act(A0@B0 + A1@B1 + b0 + b1) ----------
#define BM 64
#define BN 64
#define BK 64
__global__ void __launch_bounds__(256) gemm_fused(
    const float* __restrict__ A0, int lda0, const float* __restrict__ B0, int K0,
    const float* __restrict__ A1, int lda1, const float* __restrict__ B1, int K1,
    const float* __restrict__ bias0, const float* __restrict__ bias1,
    float* __restrict__ C, int M, int Ncols, int act_sigmoid, int ileaveD)
{
    __shared__ float As[BM][BK + 4];
    __shared__ float Bs[BK][BN + 4];
    const int tid = threadIdx.x;
    const int tx = tid % 16;
    const int ty = tid / 16;
    const int m0 = blockIdx.x * BM;
    const int n0 = blockIdx.y * BN;

    float acc[4][4];
#pragma unroll
    for (int i = 0; i < 4; i++)
#pragma unroll
        for (int j = 0; j < 4; j++) acc[i][j] = 0.0f;

    for (int pair = 0; pair < 2; pair++) {
        const float* A = pair ? A1 : A0;
        const float* B = pair ? B1 : B0;
        const int    K = pair ? K1 : K0;
        const int  lda = pair ? lda1 : lda0;
        if (A == nullptr || K == 0) continue;

        for (int k0 = 0; k0 < K; k0 += BK) {
#pragma unroll
            for (int i = 0; i < 4; i++) {
                int fid = tid + 256 * i;
                int r  = fid >> 4;
                int kc = (fid & 15) << 2;
                float4 va = *(const float4*)(A + (size_t)(m0 + r) * lda + k0 + kc);
                *(float4*)&As[r][kc] = va;
                float4 vb = *(const float4*)(B + (size_t)(k0 + r) * Ncols + n0 + kc);
                *(float4*)&Bs[r][kc] = vb;
            }
            __syncthreads();
#pragma unroll 8
            for (int k = 0; k < BK; k++) {
                float4 b = *(const float4*)&Bs[k][tx << 2];
                float a0 = As[ty * 4 + 0][k];
                float a1 = As[ty * 4 + 1][k];
                float a2 = As[ty * 4 + 2][k];
                float a3 = As[ty * 4 + 3][k];
                acc[0][0] += a0 * b.x; acc[0][1] += a0 * b.y; acc[0][2] += a0 * b.z; acc[0][3] += a0 * b.w;
                acc[1][0] += a1 * b.x; acc[1][1] += a1 * b.y; acc[1][2] += a1 * b.z; acc[1][3] += a1 * b.w;
                acc[2][0] += a2 * b.x; acc[2][1] += a2 * b.y; acc[2][2] += a2 * b.z; acc[2][3] += a2 * b.w;
                acc[3][0] += a3 * b.x; acc[3][1] += a3 * b.y; acc[3][2] += a3 * b.z; acc[3][3] += a3 * b.w;
            }
            __syncthreads();
        }
    }

#pragma unroll
    for (int i = 0; i < 4; i++) {
        int r = m0 + ty * 4 + i;
#pragma unroll
        for (int j = 0; j < 4; j++) {
            int L = n0 + tx * 4 + j;
            float v = acc[i][j];
            if (bias0) v += bias0[L];
            if (bias1) v += bias1[L];
            if (act_sigmoid) v = 1.0f / (1.0f + __expf(-v));
            int pc = L;
            if (ileaveD) pc = (L % ileaveD) * 4 + (L / ileaveD);
            C[(size_t)r * Ncols + pc] = v;
        }
    }
}

// -------- per-graph readout + 2-layer head -----------------------------------
__global__ void __launch_bounds__(128) readout_kernel(
    const float* __restrict__ H2,
    const float* __restrict__ rwW, const float* __restrict__ rwb,
    const float* __restrict__ h1W, const float* __restrict__ h1b,
    const float* __restrict__ h2W, const float* __restrict__ h2b,
    float* __restrict__ out)
{
    const int g = blockIdx.x;
    const int t = threadIdx.x;
    __shared__ float h2s[32][128];
    __shared__ float wv[32];
    __shared__ float gembs[256];
    __shared__ float y1s[128];

    for (int idx = t; idx < 32 * 128; idx += 128)
        h2s[idx >> 7][idx & 127] = H2[(size_t)g * 32 * 128 + idx];
    __syncthreads();

    const int warp = t >> 5, lane = t & 31;
    float r0 = rwW[lane], r1 = rwW[lane + 32], r2 = rwW[lane + 64], r3 = rwW[lane + 96];
    for (int mm = 0; mm < 8; mm++) {
        int m = warp * 8 + mm;
        float s = h2s[m][lane] * r0 + h2s[m][lane + 32] * r1
                + h2s[m][lane + 64] * r2 + h2s[m][lane + 96] * r3;
#pragma unroll
        for (int o = 16; o; o >>= 1) s += __shfl_down_sync(0xffffffffu, s, o);
        if (lane == 0) wv[m] = 1.0f / (1.0f + __expf(-(s + rwb[0])));
    }
    __syncthreads();

    {
        float ws = 0.0f, mx = -INFINITY;
#pragma unroll
        for (int m = 0; m < 32; m++) {
            float v = h2s[m][t];
            ws += wv[m] * v;
            mx = fmaxf(mx, v);
        }
        gembs[t] = ws;
        gembs[128 + t] = mx;
    }
    __syncthreads();

    {
        float s = h1b[t];
        for (int cc = 0; cc < 256; cc++) s += gembs[cc] * h1W[cc * 128 + t];
        y1s[t] = 1.0f / (1.0f + __expf(-s));
    }
    __syncthreads();

    if (t < 2) {
        float s = h2b[t];
        for (int j = 0; j < 128; j++) s += y1s[j] * h2W[j * 2 + t];
        out[g * 2 + t] = 1.0f / (1.0f + __expf(-s));
    }
}

// ---------------------------- launch -----------------------------------------
extern "C" void kernel_launch(void* const* d_in, const int* in_sizes, int n_in,
                              void* d_out, int out_size)
{
    const float* xn    = (const float*)d_in[0];
    const int*   nbr   = (const int*)  d_in[1];
    const float* l1Wih = (const float*)d_in[4];
    const float* l1Whh = (const float*)d_in[5];
    const float* l1b   = (const float*)d_in[6];
    const float* fs1W  = (const float*)d_in[7];
    const float* fs1b  = (const float*)d_in[8];
    const float* fn1W  = (const float*)d_in[9];
    const float* fn1b  = (const float*)d_in[10];
    const float* l2Wih = (const float*)d_in[11];
    const float* l2Whh = (const float*)d_in[12];
    const float* l2b   = (const float*)d_in[13];
    const float* fs2W  = (const float*)d_in[14];
    const float* fs2b  = (const float*)d_in[15];
    const float* fn2W  = (const float*)d_in[16];
    const float* fn2b  = (const float*)d_in[17];
    const float* rwW   = (const float*)d_in[18];
    const float* rwb   = (const float*)d_in[19];
    const float* h1W   = (const float*)d_in[20];
    const float* h1b   = (const float*)d_in[21];
    const float* h2W   = (const float*)d_in[22];
    const float* h2b   = (const float*)d_in[23];
    float* out = (float*)d_out;

    float *P1, *HN1, *H1, *P2, *HN2, *H2, *Bp1, *Bp2, *C1, *C2, *HA1, *HB1, *HA2, *HB2;
    cudaGetSymbolAddress((void**)&P1,  g_P1);
    cudaGetSymbolAddress((void**)&HN1, g_HN1);
    cudaGetSymbolAddress((void**)&H1,  g_H1);
    cudaGetSymbolAddress((void**)&P2,  g_P2);
    cudaGetSymbolAddress((void**)&HN2, g_HN2);
    cudaGetSymbolAddress((void**)&H2,  g_H2);
    cudaGetSymbolAddress((void**)&Bp1, g_Bp1);
    cudaGetSymbolAddress((void**)&Bp2, g_Bp2);
    cudaGetSymbolAddress((void**)&C1,  g_C1);
    cudaGetSymbolAddress((void**)&C2,  g_C2);
    cudaGetSymbolAddress((void**)&HA1, g_HA1);
    cudaGetSymbolAddress((void**)&HB1, g_HB1);
    cudaGetSymbolAddress((void**)&HA2, g_HA2);
    cudaGetSymbolAddress((void**)&HB2, g_HB2);

    const int smem1 = 2 * 64  * 128 * 4;   //  64 KB
    const int smem2 = 2 * 128 * 128 * 4;   // 128 KB
    cudaFuncSetAttribute(lstm_step<64>,  cudaFuncAttributeMaxDynamicSharedMemorySize, smem1);
    cudaFuncSetAttribute(lstm_step<128>, cudaFuncAttributeMaxDynamicSharedMemorySize, smem2);

    // pack recurrent weights (tf32, fragment order)
    pack_B<<<(64 * 256 + 255) / 256, 256>>>(l1Whh, Bp1, 64, 8);
    pack_B<<<(128 * 512 + 255) / 256, 256>>>(l2Whh, Bp2, 128, 16);

    // P1 = x @ Wih1 + b1  (gate-interleaved)
    gemm_fused<<<dim3(NN / 64, 256 / 64), 256>>>(
        xn, 64, l1Wih, 64, nullptr, 0, nullptr, 0, l1b, nullptr,
        P1, NN, 256, 0, 64);

    // layer1 LSTM: 16 tensor-core steps
    for (int t = 0; t < KK; t++) {
        const float* hin = (t & 1) ? HA1 : HB1;
        float* hout = (t == KK - 1) ? HN1 : ((t & 1) ? HB1 : HA1);
        lstm_step<64><<<dim3(NN / 128, 2), 256, smem1>>>(P1, Bp1, nbr, hin, hout, C1, t);
    }

    // H1 = sigmoid(x@Ws1 + HN1@Wn1 + bs1 + bn1)
    gemm_fused<<<dim3(NN / 64, 128 / 64), 256>>>(
        xn, 64, fs1W, 64, HN1, 64, fn1W, 64, fs1b, fn1b,
        H1, NN, 128, 1, 0);

    // P2 = H1 @ Wih2 + b2  (gate-interleaved)
    gemm_fused<<<dim3(NN / 64, 512 / 64), 256>>>(
        H1, 128, l2Wih, 128, nullptr, 0, nullptr, 0, l2b, nullptr,
        P2, NN, 512, 0, 128);

    // layer2 LSTM: 16 tensor-core steps
    for (int t = 0; t < KK; t++) {
        const float* hin = (t & 1) ? HA2 : HB2;
        float* hout = (t == KK - 1) ? HN2 : ((t & 1) ? HB2 : HA2);
        lstm_step<128><<<dim3(NN / 128, 4), 256, smem2>>>(P2, Bp2, nbr, hin, hout, C2, t);
    }

    // H2 = sigmoid(H1@Ws2 + HN2@Wn2 + bs2 + bn2)
    gemm_fused<<<dim3(NN / 64, 128 / 64), 256>>>(
        H1, 128, fs2W, 128, HN2, 128, fn2W, 128, fs2b, fn2b,
        H2, NN, 128, 1, 0);

    // readout + head
    readout_kernel<<<1024, 128>>>(H2, rwW, rwb, h1W, h1b, h2W, h2b, out);
}

// round 4
// speedup vs baseline: 3.4278x; 3.4278x over previous
#include <cuda_runtime.h>
#include <cuda_bf16.h>
#include <math.h>
#include <stdint.h>

#define NN 32768
#define KK 16

// ---------------- scratch (static device globals; no allocation) -------------
__device__ float g_P1 [NN * 256];   // layer1 gate preacts, gate-interleaved [n][d*4+g]
__device__ float g_HN1[NN * 64];    // layer1 LSTM output
__device__ float g_H1 [NN * 128];   // layer1 SAGE output
__device__ float g_P2 [NN * 512];   // layer2 gate preacts, gate-interleaved
__device__ float g_HN2[NN * 128];   // layer2 LSTM output
__device__ float g_H2 [NN * 128];   // layer2 SAGE output
__device__ unsigned g_Bpk1[64 * 256 / 2];    // Whh1 packed bf16 pairs, fragment order
__device__ unsigned g_Bpk2[128 * 512 / 2];   // Whh2 packed bf16 pairs, fragment order

__device__ __forceinline__ float tanh_fast(float x) {
    float y;
    asm("tanh.approx.f32 %0, %1;" : "=f"(y) : "f"(x));
    return y;
}
__device__ __forceinline__ float sig_fast(float x) {
    return 0.5f * tanh_fast(0.5f * x) + 0.5f;
}

// -------- pack Whh [k][g*D+d] -> bf16-pair fragment order --------------------
// uint idx = ((k16*(C4/8) + n8)*32 + lane)*2 + r
//   holds bf16 pair (k, k+1) with k = k16*16 + (lane&3)*2 + r*8, n = n8*8 + lane>>2
__global__ void pack_Bbf(const float* __restrict__ W, unsigned* __restrict__ Bp, int D)
{
    const int C4 = 4 * D;
    const int total = D * C4 / 2;
    int idx = blockIdx.x * blockDim.x + threadIdx.x;
    if (idx >= total) return;
    int r    = idx & 1;
    int lane = (idx >> 1) & 31;
    int g8   = idx >> 6;
    int NT8  = C4 / 8;
    int k16  = g8 / NT8;
    int n8   = g8 % NT8;
    int k = k16 * 16 + (lane & 3) * 2 + r * 8;
    int n = n8 * 8 + (lane >> 2);
    int d = n >> 2, g = n & 3;
    float e0 = W[(size_t)k * C4 + g * D + d];
    float e1 = W[(size_t)(k + 1) * C4 + g * D + d];
    __nv_bfloat162 p = __floats2bfloat162_rn(e0, e1);
    Bp[idx] = *(unsigned*)&p;
}

// -------- persistent bf16 tensor-core LSTM -----------------------------------
// One CTA = 32 nodes, 512 threads (16 warps: 2 m-slabs x 8 n-slabs).
// h lives in smem (bf16) across all 16 steps; c lives in registers; full Whh
// (bf16 fragment-packed) lives in smem. Per step: ldmatrix + m16n8k16 bf16 mma,
// epilogue gathers fp32 P[nbr] and does the LSTM cell update via pair shuffles.
template <int DIM>
__global__ void __launch_bounds__(512, 1) lstm_persist(
    const float* __restrict__ P,      // [NN][4*DIM] gate-interleaved fp32
    const unsigned* __restrict__ Bpk, // packed bf16 Whh
    const int*   __restrict__ nbr,    // [NN][16]
    float*       __restrict__ HN)     // [NN][DIM] final h
{
    constexpr int C4     = 4 * DIM;
    constexpr int K16    = DIM / 16;
    constexpr int NT8    = C4 / 8;     // total 8-col groups
    constexpr int WC     = C4 / 8;     // cols per warp (8 n-slabs)
    constexpr int NTILES = WC / 8;
    constexpr int MB     = 32;
    constexpr int HP     = DIM + 8;    // h row pitch in bf16 (272B: conflict-free ldmatrix)

    extern __shared__ unsigned smem_u[];
    unsigned*       Bsm = smem_u;                              // DIM*C4/2 uints
    __nv_bfloat16*  Hs  = (__nv_bfloat16*)(smem_u + DIM * C4 / 2);  // [MB][HP]

    const int tid  = threadIdx.x;
    const int lane = tid & 31;
    const int warp = tid >> 5;
    const int wm   = warp >> 3;     // 0..1 : 16-row slab
    const int wn   = warp & 7;      // 0..7 : WC-col slab
    const int base = blockIdx.x * MB;

    // load packed B into smem (one time; reused 16 steps)
    {
        const uint4* src = (const uint4*)Bpk;
        uint4* dst = (uint4*)Bsm;
        for (int i = tid; i < DIM * C4 / 8; i += 512) dst[i] = src[i];
    }
    __syncthreads();

    float creg[NTILES][2];
#pragma unroll
    for (int nt = 0; nt < NTILES; nt++) { creg[nt][0] = 0.0f; creg[nt][1] = 0.0f; }

    const int  r0 = wm * 16 + (lane >> 2);
    const int  r1 = r0 + 8;
    const bool evenp = ((lane & 1) == 0);
    const int  arow = wm * 16 + (lane & 15);
    const int  acolb = (lane >> 4) << 3;

    for (int t = 0; t < KK; t++) {
        float acc[NTILES][4];
#pragma unroll
        for (int nt = 0; nt < NTILES; nt++) {
            acc[nt][0] = acc[nt][1] = acc[nt][2] = acc[nt][3] = 0.0f;
        }

        if (t > 0) {
#pragma unroll
            for (int k16 = 0; k16 < K16; k16++) {
                unsigned a0, a1, a2, a3;
                unsigned addr =
                    (unsigned)__cvta_generic_to_shared(&Hs[arow * HP + k16 * 16 + acolb]);
                asm volatile(
                    "ldmatrix.sync.aligned.m8n8.x4.shared.b16 {%0,%1,%2,%3}, [%4];"
                    : "=r"(a0), "=r"(a1), "=r"(a2), "=r"(a3) : "r"(addr));
#pragma unroll
                for (int nt = 0; nt < NTILES; nt++) {
                    uint2 b = ((const uint2*)Bsm)[(k16 * NT8 + wn * NTILES + nt) * 32 + lane];
                    asm volatile(
                        "mma.sync.aligned.m16n8k16.row.col.f32.bf16.bf16.f32 "
                        "{%0,%1,%2,%3},{%4,%5,%6,%7},{%8,%9},{%0,%1,%2,%3};"
                        : "+f"(acc[nt][0]), "+f"(acc[nt][1]), "+f"(acc[nt][2]), "+f"(acc[nt][3])
                        : "r"(a0), "r"(a1), "r"(a2), "r"(a3), "r"(b.x), "r"(b.y));
                }
            }
        }
        __syncthreads();   // all reads of Hs (h_{t-1}) complete

        const int j0 = __ldg(&nbr[(base + r0) * KK + t]);
        const int j1 = __ldg(&nbr[(base + r1) * KK + t]);
#pragma unroll
        for (int nt = 0; nt < NTILES; nt++) {
            int ci = wn * WC + nt * 8 + 2 * (lane & 3);
            int d  = ci >> 2;
            float2 p0 = *(const float2*)&P[(size_t)j0 * C4 + ci];
            float2 p1 = *(const float2*)&P[(size_t)j1 * C4 + ci];
            float g00 = acc[nt][0] + p0.x;   // even lane: i | odd lane: g
            float g01 = acc[nt][1] + p0.y;   // even lane: f | odd lane: o
            float g10 = acc[nt][2] + p1.x;
            float g11 = acc[nt][3] + p1.y;
            float x00 = evenp ? sig_fast(g00) : tanh_fast(g00);
            float x01 = sig_fast(g01);
            float x10 = evenp ? sig_fast(g10) : tanh_fast(g10);
            float x11 = sig_fast(g11);
            float y00 = __shfl_xor_sync(0xffffffffu, x00, 1);  // even view: tanh(g)
            float y10 = __shfl_xor_sync(0xffffffffu, x10, 1);
            float cn0 = x01 * creg[nt][0] + x00 * y00;         // even: sf*c + si*tg
            float cn1 = x11 * creg[nt][1] + x10 * y10;
            float tc0 = tanh_fast(cn0);
            float tc1 = tanh_fast(cn1);
            float tz0 = __shfl_xor_sync(0xffffffffu, tc0, 1);  // odd view: tanh(c)
            float tz1 = __shfl_xor_sync(0xffffffffu, tc1, 1);
            if (evenp) {
                creg[nt][0] = cn0;
                creg[nt][1] = cn1;
            } else {
                float h0 = x01 * tz0;                          // so * tanh(c)
                float h1 = x11 * tz1;
                Hs[r0 * HP + d] = __float2bfloat16(h0);
                Hs[r1 * HP + d] = __float2bfloat16(h1);
                if (t == KK - 1) {
                    HN[(size_t)(base + r0) * DIM + d] = h0;
                    HN[(size_t)(base + r1) * DIM + d] = h1;
                }
            }
        }
        __syncthreads();   // h_t visible before next step's mma
    }
}

// -------- generic fused SIMT GEMM: C = act(A0@B0 + A1@B1 + b0 + b1) ----------
#define BM 64
#define BN 64
#define BK 64
__global__ void __launch_bounds__(256) gemm_fused(
    const float* __restrict__ A0, int lda0, const float* __restrict__ B0, int K0,
    const float* __restrict__ A1, int lda1, const float* __restrict__ B1, int K1,
    const float* __restrict__ bias0, const float* __restrict__ bias1,
    float* __restrict__ C, int M, int Ncols, int act_sigmoid, int ileaveD)
{
    __shared__ float As[BM][BK + 4];
    __shared__ float Bs[BK][BN + 4];
    const int tid = threadIdx.x;
    const int tx = tid % 16;
    const int ty = tid / 16;
    const int m0 = blockIdx.x * BM;
    const int n0 = blockIdx.y * BN;

    float acc[4][4];
#pragma unroll
    for (int i = 0; i < 4; i++)
#pragma unroll
        for (int j = 0; j < 4; j++) acc[i][j] = 0.0f;

    for (int pair = 0; pair < 2; pair++) {
        const float* A = pair ? A1 : A0;
        const float* B = pair ? B1 : B0;
        const int    K = pair ? K1 : K0;
        const int  lda = pair ? lda1 : lda0;
        if (A == nullptr || K == 0) continue;

        for (int k0 = 0; k0 < K; k0 += BK) {
#pragma unroll
            for (int i = 0; i < 4; i++) {
                int fid = tid + 256 * i;
                int r  = fid >> 4;
                int kc = (fid & 15) << 2;
                float4 va = *(const float4*)(A + (size_t)(m0 + r) * lda + k0 + kc);
                *(float4*)&As[r][kc] = va;
                float4 vb = *(const float4*)(B + (size_t)(k0 + r) * Ncols + n0 + kc);
                *(float4*)&Bs[r][kc] = vb;
            }
            __syncthreads();
#pragma unroll 8
            for (int k = 0; k < BK; k++) {
                float4 b = *(const float4*)&Bs[k][tx << 2];
                float a0 = As[ty * 4 + 0][k];
                float a1 = As[ty * 4 + 1][k];
                float a2 = As[ty * 4 + 2][k];
                float a3 = As[ty * 4 + 3][k];
                acc[0][0] += a0 * b.x; acc[0][1] += a0 * b.y; acc[0][2] += a0 * b.z; acc[0][3] += a0 * b.w;
                acc[1][0] += a1 * b.x; acc[1][1] += a1 * b.y; acc[1][2] += a1 * b.z; acc[1][3] += a1 * b.w;
                acc[2][0] += a2 * b.x; acc[2][1] += a2 * b.y; acc[2][2] += a2 * b.z; acc[2][3] += a2 * b.w;
                acc[3][0] += a3 * b.x; acc[3][1] += a3 * b.y; acc[3][2] += a3 * b.z; acc[3][3] += a3 * b.w;
            }
            __syncthreads();
        }
    }

#pragma unroll
    for (int i = 0; i < 4; i++) {
        int r = m0 + ty * 4 + i;
#pragma unroll
        for (int j = 0; j < 4; j++) {
            int L = n0 + tx * 4 + j;
            float v = acc[i][j];
            if (bias0) v += bias0[L];
            if (bias1) v += bias1[L];
            if (act_sigmoid) v = 1.0f / (1.0f + __expf(-v));
            int pc = L;
            if (ileaveD) pc = (L % ileaveD) * 4 + (L / ileaveD);
            C[(size_t)r * Ncols + pc] = v;
        }
    }
}

// -------- per-graph readout + 2-layer head -----------------------------------
__global__ void __launch_bounds__(128) readout_kernel(
    const float* __restrict__ H2,
    const float* __restrict__ rwW, const float* __restrict__ rwb,
    const float* __restrict__ h1W, const float* __restrict__ h1b,
    const float* __restrict__ h2W, const float* __restrict__ h2b,
    float* __restrict__ out)
{
    const int g = blockIdx.x;
    const int t = threadIdx.x;
    __shared__ float h2s[32][128];
    __shared__ float wv[32];
    __shared__ float gembs[256];
    __shared__ float y1s[128];

    for (int idx = t; idx < 32 * 128; idx += 128)
        h2s[idx >> 7][idx & 127] = H2[(size_t)g * 32 * 128 + idx];
    __syncthreads();

    const int warp = t >> 5, lane = t & 31;
    float r0 = rwW[lane], r1 = rwW[lane + 32], r2 = rwW[lane + 64], r3 = rwW[lane + 96];
    for (int mm = 0; mm < 8; mm++) {
        int m = warp * 8 + mm;
        float s = h2s[m][lane] * r0 + h2s[m][lane + 32] * r1
                + h2s[m][lane + 64] * r2 + h2s[m][lane + 96] * r3;
#pragma unroll
        for (int o = 16; o; o >>= 1) s += __shfl_down_sync(0xffffffffu, s, o);
        if (lane == 0) wv[m] = 1.0f / (1.0f + __expf(-(s + rwb[0])));
    }
    __syncthreads();

    {
        float ws = 0.0f, mx = -INFINITY;
#pragma unroll
        for (int m = 0; m < 32; m++) {
            float v = h2s[m][t];
            ws += wv[m] * v;
            mx = fmaxf(mx, v);
        }
        gembs[t] = ws;
        gembs[128 + t] = mx;
    }
    __syncthreads();

    {
        float s = h1b[t];
        for (int cc = 0; cc < 256; cc++) s += gembs[cc] * h1W[cc * 128 + t];
        y1s[t] = 1.0f / (1.0f + __expf(-s));
    }
    __syncthreads();

    if (t < 2) {
        float s = h2b[t];
        for (int j = 0; j < 128; j++) s += y1s[j] * h2W[j * 2 + t];
        out[g * 2 + t] = 1.0f / (1.0f + __expf(-s));
    }
}

// ---------------------------- launch -----------------------------------------
extern "C" void kernel_launch(void* const* d_in, const int* in_sizes, int n_in,
                              void* d_out, int out_size)
{
    const float* xn    = (const float*)d_in[0];
    const int*   nbr   = (const int*)  d_in[1];
    const float* l1Wih = (const float*)d_in[4];
    const float* l1Whh = (const float*)d_in[5];
    const float* l1b   = (const float*)d_in[6];
    const float* fs1W  = (const float*)d_in[7];
    const float* fs1b  = (const float*)d_in[8];
    const float* fn1W  = (const float*)d_in[9];
    const float* fn1b  = (const float*)d_in[10];
    const float* l2Wih = (const float*)d_in[11];
    const float* l2Whh = (const float*)d_in[12];
    const float* l2b   = (const float*)d_in[13];
    const float* fs2W  = (const float*)d_in[14];
    const float* fs2b  = (const float*)d_in[15];
    const float* fn2W  = (const float*)d_in[16];
    const float* fn2b  = (const float*)d_in[17];
    const float* rwW   = (const float*)d_in[18];
    const float* rwb   = (const float*)d_in[19];
    const float* h1W   = (const float*)d_in[20];
    const float* h1b   = (const float*)d_in[21];
    const float* h2W   = (const float*)d_in[22];
    const float* h2b   = (const float*)d_in[23];
    float* out = (float*)d_out;

    float *P1, *HN1, *H1, *P2, *HN2, *H2;
    unsigned *Bpk1, *Bpk2;
    cudaGetSymbolAddress((void**)&P1,   g_P1);
    cudaGetSymbolAddress((void**)&HN1,  g_HN1);
    cudaGetSymbolAddress((void**)&H1,   g_H1);
    cudaGetSymbolAddress((void**)&P2,   g_P2);
    cudaGetSymbolAddress((void**)&HN2,  g_HN2);
    cudaGetSymbolAddress((void**)&H2,   g_H2);
    cudaGetSymbolAddress((void**)&Bpk1, g_Bpk1);
    cudaGetSymbolAddress((void**)&Bpk2, g_Bpk2);

    // smem: packed B (bf16) + h buffer [32][DIM+8] bf16
    const int smem1 = 64 * 256 * 2 + 32 * (64 + 8) * 2;     //  37376 B
    const int smem2 = 128 * 512 * 2 + 32 * (128 + 8) * 2;   // 139776 B
    cudaFuncSetAttribute(lstm_persist<64>,  cudaFuncAttributeMaxDynamicSharedMemorySize, smem1);
    cudaFuncSetAttribute(lstm_persist<128>, cudaFuncAttributeMaxDynamicSharedMemorySize, smem2);

    // pack recurrent weights (bf16 fragment order)
    pack_Bbf<<<(64 * 256 / 2 + 255) / 256, 256>>>(l1Whh, Bpk1, 64);
    pack_Bbf<<<(128 * 512 / 2 + 255) / 256, 256>>>(l2Whh, Bpk2, 128);

    // P1 = x @ Wih1 + b1  (gate-interleaved)
    gemm_fused<<<dim3(NN / 64, 256 / 64), 256>>>(
        xn, 64, l1Wih, 64, nullptr, 0, nullptr, 0, l1b, nullptr,
        P1, NN, 256, 0, 64);

    // layer1 LSTM (persistent, tensor cores)
    lstm_persist<64><<<NN / 32, 512, smem1>>>(P1, Bpk1, nbr, HN1);

    // H1 = sigmoid(x@Ws1 + HN1@Wn1 + bs1 + bn1)
    gemm_fused<<<dim3(NN / 64, 128 / 64), 256>>>(
        xn, 64, fs1W, 64, HN1, 64, fn1W, 64, fs1b, fn1b,
        H1, NN, 128, 1, 0);

    // P2 = H1 @ Wih2 + b2  (gate-interleaved)
    gemm_fused<<<dim3(NN / 64, 512 / 64), 256>>>(
        H1, 128, l2Wih, 128, nullptr, 0, nullptr, 0, l2b, nullptr,
        P2, NN, 512, 0, 128);

    // layer2 LSTM (persistent, tensor cores)
    lstm_persist<128><<<NN / 32, 512, smem2>>>(P2, Bpk2, nbr, HN2);

    // H2 = sigmoid(H1@Ws2 + HN2@Wn2 + bs2 + bn2)
    gemm_fused<<<dim3(NN / 64, 128 / 64), 256>>>(
        H1, 128, fs2W, 128, HN2, 128, fn2W, 128, fs2b, fn2b,
        H2, NN, 128, 1, 0);

    // readout + head
    readout_kernel<<<1024, 128>>>(H2, rwW, rwb, h1W, h1b, h2W, h2b, out);
}

// round 5
// speedup vs baseline: 4.5030x; 1.3136x over previous
#include <cuda_runtime.h>
#include <cuda_bf16.h>
#include <math.h>
#include <stdint.h>

#define NN 32768
#define KK 16

// ---------------- scratch (static device globals; no allocation) -------------
__device__ unsigned g_Pu1[NN * 128];    // layer1 gate preacts, bf16 pairs (256 cols)
__device__ unsigned g_Pu2[NN * 256];    // layer2 gate preacts, bf16 pairs (512 cols)
__device__ float g_HN1[NN * 64];        // layer1 LSTM output
__device__ float g_H1 [NN * 128];       // layer1 SAGE output
__device__ float g_HN2[NN * 128];       // layer2 LSTM output
__device__ float g_H2 [NN * 128];       // layer2 SAGE output
// packed bf16 weights (mma fragment order)
__device__ unsigned g_Wih1[64 * 256 / 2];
__device__ unsigned g_Wfs1[64 * 128 / 2];
__device__ unsigned g_Wfn1[64 * 128 / 2];
__device__ unsigned g_Whh1[64 * 256 / 2];
__device__ unsigned g_Wih2[128 * 512 / 2];
__device__ unsigned g_Wfs2[128 * 128 / 2];
__device__ unsigned g_Wfn2[128 * 128 / 2];
__device__ unsigned g_Whh2[128 * 512 / 2];

__device__ __forceinline__ float tanh_fast(float x) {
    float y;
    asm("tanh.approx.f32 %0, %1;" : "=f"(y) : "f"(x));
    return y;
}
__device__ __forceinline__ float sig_fast(float x) {
    return 0.5f * tanh_fast(0.5f * x) + 0.5f;
}

// -------- pack W [K][N] -> bf16-pair mma fragment order ----------------------
// uint idx = ((k16*(N/8) + n8)*32 + lane)*2 + r holds bf16 pair (k,k+1) with
//   k = k16*16 + (lane&3)*2 + r*8, phys col n = n8*8 + (lane>>2).
// Phys col n sources logical col (n&3)*ileaveD + (n>>2) when ileaveD != 0
// (bakes the gate-interleave permutation into the weights).
__global__ void pack_W(const float* __restrict__ W, unsigned* __restrict__ Bp,
                       int K, int N, int ileaveD)
{
    int idx = blockIdx.x * blockDim.x + threadIdx.x;
    if (idx >= K * N / 2) return;
    int r    = idx & 1;
    int lane = (idx >> 1) & 31;
    int g8   = idx >> 6;
    int NT8  = N / 8;
    int k16  = g8 / NT8;
    int n8   = g8 % NT8;
    int k = k16 * 16 + (lane & 3) * 2 + r * 8;
    int n = n8 * 8 + (lane >> 2);
    int col = ileaveD ? (n & 3) * ileaveD + (n >> 2) : n;
    float e0 = W[(size_t)k * N + col];
    float e1 = W[(size_t)(k + 1) * N + col];
    __nv_bfloat162 p = __floats2bfloat162_rn(e0, e1);
    Bp[idx] = *(unsigned*)&p;
}

// -------- bf16 tensor-core fused GEMM ----------------------------------------
// C = act(A0@B0 + A1@B1 + bias0 + bias1). BM=128, BN=128 per CTA, 256 threads,
// 8 warps = 8 m-slabs of 16 rows; B read directly from packed global (L1-hot).
// Output either fp32 (Cf) or bf16 pairs (Cb). Column permutation baked into B;
// biases indexed through the inverse permutation.
__global__ void __launch_bounds__(256) gemm_tc(
    const float* __restrict__ A0, int K0, const unsigned* __restrict__ Bp0,
    const float* __restrict__ A1, int K1, const unsigned* __restrict__ Bp1,
    const float* __restrict__ bias0, const float* __restrict__ bias1,
    float* __restrict__ Cf, unsigned* __restrict__ Cb,
    int Ntot, int act_sigmoid, int ileaveD)
{
    __shared__ __nv_bfloat16 As[128 * 136];

    const int tid  = threadIdx.x;
    const int lane = tid & 31;
    const int warp = tid >> 5;
    const int m0   = blockIdx.x * 128;
    const int nb0  = blockIdx.y * 16;      // n8 base
    const int NT8  = Ntot / 8;

    float acc[16][4];
#pragma unroll
    for (int nt = 0; nt < 16; nt++)
#pragma unroll
        for (int q = 0; q < 4; q++) acc[nt][q] = 0.0f;

    for (int pair = 0; pair < 2; pair++) {
        const float* A = pair ? A1 : A0;
        const unsigned* Bp = pair ? Bp1 : Bp0;
        const int K = pair ? K1 : K0;
        if (A == nullptr || K == 0) continue;
        const int KP = K + 8;
        const int K16 = K / 16;
        const int KC = K / 4;

        __syncthreads();
        for (int i = tid; i < 128 * KC; i += 256) {
            int row = i / KC, cc = i % KC;
            float4 v = *(const float4*)(A + (size_t)(m0 + row) * K + cc * 4);
            __nv_bfloat162 lo = __floats2bfloat162_rn(v.x, v.y);
            __nv_bfloat162 hi = __floats2bfloat162_rn(v.z, v.w);
            uint2 u = {*(unsigned*)&lo, *(unsigned*)&hi};
            *(uint2*)&As[row * KP + cc * 4] = u;
        }
        __syncthreads();

        const int arow  = warp * 16 + (lane & 15);
        const int acolb = (lane >> 4) << 3;
        for (int k16 = 0; k16 < K16; k16++) {
            unsigned a0, a1, a2, a3;
            unsigned addr =
                (unsigned)__cvta_generic_to_shared(&As[arow * KP + k16 * 16 + acolb]);
            asm volatile(
                "ldmatrix.sync.aligned.m8n8.x4.shared.b16 {%0,%1,%2,%3}, [%4];"
                : "=r"(a0), "=r"(a1), "=r"(a2), "=r"(a3) : "r"(addr));
#pragma unroll
            for (int nt = 0; nt < 16; nt++) {
                uint2 b = ((const uint2*)Bp)[(k16 * NT8 + nb0 + nt) * 32 + lane];
                asm volatile(
                    "mma.sync.aligned.m16n8k16.row.col.f32.bf16.bf16.f32 "
                    "{%0,%1,%2,%3},{%4,%5,%6,%7},{%8,%9},{%0,%1,%2,%3};"
                    : "+f"(acc[nt][0]), "+f"(acc[nt][1]), "+f"(acc[nt][2]), "+f"(acc[nt][3])
                    : "r"(a0), "r"(a1), "r"(a2), "r"(a3), "r"(b.x), "r"(b.y));
            }
        }
    }

    // epilogue
    const int r0 = m0 + warp * 16 + (lane >> 2);
    const int r1 = r0 + 8;
#pragma unroll
    for (int nt = 0; nt < 16; nt++) {
        int ci = (nb0 + nt) * 8 + 2 * (lane & 3);
        int lgA = ileaveD ? (ci & 3) * ileaveD + (ci >> 2) : ci;
        int cj = ci + 1;
        int lgB = ileaveD ? (cj & 3) * ileaveD + (cj >> 2) : cj;
        float bA = (bias0 ? bias0[lgA] : 0.0f) + (bias1 ? bias1[lgA] : 0.0f);
        float bB = (bias0 ? bias0[lgB] : 0.0f) + (bias1 ? bias1[lgB] : 0.0f);
        float v00 = acc[nt][0] + bA, v01 = acc[nt][1] + bB;
        float v10 = acc[nt][2] + bA, v11 = acc[nt][3] + bB;
        if (act_sigmoid) {
            v00 = 1.0f / (1.0f + __expf(-v00));
            v01 = 1.0f / (1.0f + __expf(-v01));
            v10 = 1.0f / (1.0f + __expf(-v10));
            v11 = 1.0f / (1.0f + __expf(-v11));
        }
        if (Cb) {
            __nv_bfloat162 p0 = __floats2bfloat162_rn(v00, v01);
            __nv_bfloat162 p1 = __floats2bfloat162_rn(v10, v11);
            Cb[(size_t)r0 * (Ntot / 2) + (ci >> 1)] = *(unsigned*)&p0;
            Cb[(size_t)r1 * (Ntot / 2) + (ci >> 1)] = *(unsigned*)&p1;
        } else {
            float2 f0 = {v00, v01}, f1 = {v10, v11};
            *(float2*)&Cf[(size_t)r0 * Ntot + ci] = f0;
            *(float2*)&Cf[(size_t)r1 * Ntot + ci] = f1;
        }
    }
}

// -------- persistent bf16 tensor-core LSTM -----------------------------------
// One CTA = 32 nodes. h double-buffered in smem (bf16); c in registers; full
// packed Whh in smem. Per step: prefetch P[nbr] gather (independent of h) to
// hide L2 latency behind the MMA phase; ldmatrix + m16n8k16 mma; lane-pair
// shuffle cell update; ONE syncthreads per step (write buffer != read buffer).
template <int DIM, int WN, int NTHREADS>
__global__ void __launch_bounds__(NTHREADS, (NTHREADS == 256) ? 2 : 1) lstm_persist(
    const unsigned* __restrict__ Pu,  // [NN][2*DIM] bf16 pairs (4*DIM cols)
    const unsigned* __restrict__ Bpk, // packed bf16 Whh
    const int*      __restrict__ nbr, // [NN][16]
    float*          __restrict__ HN)  // [NN][DIM] final h
{
    constexpr int C4     = 4 * DIM;
    constexpr int C2     = 2 * DIM;
    constexpr int K16    = DIM / 16;
    constexpr int NT8    = C4 / 8;
    constexpr int WC     = C4 / WN;    // 64
    constexpr int NTILES = WC / 8;     // 8
    constexpr int HP     = DIM + 8;

    extern __shared__ unsigned smem_u[];
    unsigned*       Bsm = smem_u;                                   // DIM*C4/2 uints
    __nv_bfloat16*  Hs0 = (__nv_bfloat16*)(smem_u + DIM * C4 / 2);  // [32][HP]
    __nv_bfloat16*  Hs1 = Hs0 + 32 * HP;

    const int tid  = threadIdx.x;
    const int lane = tid & 31;
    const int warp = tid >> 5;
    const int wm   = warp / WN;     // 0..1 : 16-row slab
    const int wn   = warp % WN;     // 0..WN-1 : WC-col slab
    const int base = blockIdx.x * 32;

    // load packed B into smem (one time; reused all 16 steps)
    for (int i = tid; i < DIM * C4 / 8; i += NTHREADS)
        ((uint4*)Bsm)[i] = ((const uint4*)Bpk)[i];
    __syncthreads();

    float creg[NTILES][2];
#pragma unroll
    for (int nt = 0; nt < NTILES; nt++) { creg[nt][0] = 0.0f; creg[nt][1] = 0.0f; }

    const int  r0 = wm * 16 + (lane >> 2);
    const int  r1 = r0 + 8;
    const bool evenp = ((lane & 1) == 0);
    const int  arow  = wm * 16 + (lane & 15);
    const int  acolb = (lane >> 4) << 3;

    for (int t = 0; t < KK; t++) {
        // ---- prefetch P gather (independent of h; hides behind MMA) --------
        const int j0 = __ldg(&nbr[(base + r0) * KK + t]);
        const int j1 = __ldg(&nbr[(base + r1) * KK + t]);
        unsigned pp0[NTILES], pp1[NTILES];
#pragma unroll
        for (int nt = 0; nt < NTILES; nt++) {
            int cu = ((wn * WC + nt * 8) >> 1) + (lane & 3);
            pp0[nt] = __ldg(&Pu[(size_t)j0 * C2 + cu]);
            pp1[nt] = __ldg(&Pu[(size_t)j1 * C2 + cu]);
        }

        float acc[NTILES][4];
#pragma unroll
        for (int nt = 0; nt < NTILES; nt++)
            acc[nt][0] = acc[nt][1] = acc[nt][2] = acc[nt][3] = 0.0f;

        if (t > 0) {
            const __nv_bfloat16* Hr = (t & 1) ? Hs1 : Hs0;
#pragma unroll
            for (int k16 = 0; k16 < K16; k16++) {
                unsigned a0, a1, a2, a3;
                unsigned addr =
                    (unsigned)__cvta_generic_to_shared(&Hr[arow * HP + k16 * 16 + acolb]);
                asm volatile(
                    "ldmatrix.sync.aligned.m8n8.x4.shared.b16 {%0,%1,%2,%3}, [%4];"
                    : "=r"(a0), "=r"(a1), "=r"(a2), "=r"(a3) : "r"(addr));
#pragma unroll
                for (int nt = 0; nt < NTILES; nt++) {
                    uint2 b = ((const uint2*)Bsm)[(k16 * NT8 + wn * NTILES + nt) * 32 + lane];
                    asm volatile(
                        "mma.sync.aligned.m16n8k16.row.col.f32.bf16.bf16.f32 "
                        "{%0,%1,%2,%3},{%4,%5,%6,%7},{%8,%9},{%0,%1,%2,%3};"
                        : "+f"(acc[nt][0]), "+f"(acc[nt][1]), "+f"(acc[nt][2]), "+f"(acc[nt][3])
                        : "r"(a0), "r"(a1), "r"(a2), "r"(a3), "r"(b.x), "r"(b.y));
                }
            }
        }

        // ---- epilogue: cell update; writes go to the OTHER h buffer --------
        __nv_bfloat16* Hw = (t & 1) ? Hs0 : Hs1;
#pragma unroll
        for (int nt = 0; nt < NTILES; nt++) {
            int ci = wn * WC + nt * 8 + 2 * (lane & 3);
            int d  = ci >> 2;
            float2 p0 = __bfloat1622float2(*(__nv_bfloat162*)&pp0[nt]);
            float2 p1 = __bfloat1622float2(*(__nv_bfloat162*)&pp1[nt]);
            float g00 = acc[nt][0] + p0.x;   // even lane: i | odd lane: g
            float g01 = acc[nt][1] + p0.y;   // even lane: f | odd lane: o
            float g10 = acc[nt][2] + p1.x;
            float g11 = acc[nt][3] + p1.y;
            float x00 = evenp ? sig_fast(g00) : tanh_fast(g00);
            float x01 = sig_fast(g01);
            float x10 = evenp ? sig_fast(g10) : tanh_fast(g10);
            float x11 = sig_fast(g11);
            float y00 = __shfl_xor_sync(0xffffffffu, x00, 1);  // even view: tanh(g)
            float y10 = __shfl_xor_sync(0xffffffffu, x10, 1);
            float cn0 = x01 * creg[nt][0] + x00 * y00;         // even: sf*c + si*tg
            float cn1 = x11 * creg[nt][1] + x10 * y10;
            float tc0 = tanh_fast(cn0);
            float tc1 = tanh_fast(cn1);
            float tz0 = __shfl_xor_sync(0xffffffffu, tc0, 1);  // odd view: tanh(c)
            float tz1 = __shfl_xor_sync(0xffffffffu, tc1, 1);
            if (evenp) {
                creg[nt][0] = cn0;
                creg[nt][1] = cn1;
            } else {
                float h0 = x01 * tz0;                          // so * tanh(c)
                float h1 = x11 * tz1;
                Hw[r0 * HP + d] = __float2bfloat16(h0);
                Hw[r1 * HP + d] = __float2bfloat16(h1);
                if (t == KK - 1) {
                    HN[(size_t)(base + r0) * DIM + d] = h0;
                    HN[(size_t)(base + r1) * DIM + d] = h1;
                }
            }
        }
        __syncthreads();   // h_t visible before next step's ldmatrix
    }
}

// -------- per-graph readout + 2-layer head -----------------------------------
__global__ void __launch_bounds__(128) readout_kernel(
    const float* __restrict__ H2,
    const float* __restrict__ rwW, const float* __restrict__ rwb,
    const float* __restrict__ h1W, const float* __restrict__ h1b,
    const float* __restrict__ h2W, const float* __restrict__ h2b,
    float* __restrict__ out)
{
    const int g = blockIdx.x;
    const int t = threadIdx.x;
    __shared__ float h2s[32][128];
    __shared__ float wv[32];
    __shared__ float gembs[256];
    __shared__ float y1s[128];

    for (int idx = t; idx < 32 * 128; idx += 128)
        h2s[idx >> 7][idx & 127] = H2[(size_t)g * 32 * 128 + idx];
    __syncthreads();

    const int warp = t >> 5, lane = t & 31;
    float r0 = rwW[lane], r1 = rwW[lane + 32], r2 = rwW[lane + 64], r3 = rwW[lane + 96];
    for (int mm = 0; mm < 8; mm++) {
        int m = warp * 8 + mm;
        float s = h2s[m][lane] * r0 + h2s[m][lane + 32] * r1
                + h2s[m][lane + 64] * r2 + h2s[m][lane + 96] * r3;
#pragma unroll
        for (int o = 16; o; o >>= 1) s += __shfl_down_sync(0xffffffffu, s, o);
        if (lane == 0) wv[m] = 1.0f / (1.0f + __expf(-(s + rwb[0])));
    }
    __syncthreads();

    {
        float ws = 0.0f, mx = -INFINITY;
#pragma unroll
        for (int m = 0; m < 32; m++) {
            float v = h2s[m][t];
            ws += wv[m] * v;
            mx = fmaxf(mx, v);
        }
        gembs[t] = ws;
        gembs[128 + t] = mx;
    }
    __syncthreads();

    {
        float s = h1b[t];
        for (int cc = 0; cc < 256; cc++) s += gembs[cc] * h1W[cc * 128 + t];
        y1s[t] = 1.0f / (1.0f + __expf(-s));
    }
    __syncthreads();

    if (t < 2) {
        float s = h2b[t];
        for (int j = 0; j < 128; j++) s += y1s[j] * h2W[j * 2 + t];
        out[g * 2 + t] = 1.0f / (1.0f + __expf(-s));
    }
}

// ---------------------------- launch -----------------------------------------
extern "C" void kernel_launch(void* const* d_in, const int* in_sizes, int n_in,
                              void* d_out, int out_size)
{
    const float* xn    = (const float*)d_in[0];
    const int*   nbr   = (const int*)  d_in[1];
    const float* l1Wih = (const float*)d_in[4];
    const float* l1Whh = (const float*)d_in[5];
    const float* l1b   = (const float*)d_in[6];
    const float* fs1W  = (const float*)d_in[7];
    const float* fs1b  = (const float*)d_in[8];
    const float* fn1W  = (const float*)d_in[9];
    const float* fn1b  = (const float*)d_in[10];
    const float* l2Wih = (const float*)d_in[11];
    const float* l2Whh = (const float*)d_in[12];
    const float* l2b   = (const float*)d_in[13];
    const float* fs2W  = (const float*)d_in[14];
    const float* fs2b  = (const float*)d_in[15];
    const float* fn2W  = (const float*)d_in[16];
    const float* fn2b  = (const float*)d_in[17];
    const float* rwW   = (const float*)d_in[18];
    const float* rwb   = (const float*)d_in[19];
    const float* h1W   = (const float*)d_in[20];
    const float* h1b   = (const float*)d_in[21];
    const float* h2W   = (const float*)d_in[22];
    const float* h2b   = (const float*)d_in[23];
    float* out = (float*)d_out;

    unsigned *Pu1, *Pu2, *Wih1, *Wfs1, *Wfn1, *Whh1, *Wih2, *Wfs2, *Wfn2, *Whh2;
    float *HN1, *H1, *HN2, *H2;
    cudaGetSymbolAddress((void**)&Pu1,  g_Pu1);
    cudaGetSymbolAddress((void**)&Pu2,  g_Pu2);
    cudaGetSymbolAddress((void**)&HN1,  g_HN1);
    cudaGetSymbolAddress((void**)&H1,   g_H1);
    cudaGetSymbolAddress((void**)&HN2,  g_HN2);
    cudaGetSymbolAddress((void**)&H2,   g_H2);
    cudaGetSymbolAddress((void**)&Wih1, g_Wih1);
    cudaGetSymbolAddress((void**)&Wfs1, g_Wfs1);
    cudaGetSymbolAddress((void**)&Wfn1, g_Wfn1);
    cudaGetSymbolAddress((void**)&Whh1, g_Whh1);
    cudaGetSymbolAddress((void**)&Wih2, g_Wih2);
    cudaGetSymbolAddress((void**)&Wfs2, g_Wfs2);
    cudaGetSymbolAddress((void**)&Wfn2, g_Wfn2);
    cudaGetSymbolAddress((void**)&Whh2, g_Whh2);

    // smem: packed Whh + double-buffered h [2][32][DIM+8] bf16
    const int smem1 = 64 * 256 * 2 + 2 * 32 * (64 + 8) * 2;     //  41984 B
    const int smem2 = 128 * 512 * 2 + 2 * 32 * (128 + 8) * 2;   // 148480 B
    cudaFuncSetAttribute((const void*)lstm_persist<64, 4, 256>,
                         cudaFuncAttributeMaxDynamicSharedMemorySize, smem1);
    cudaFuncSetAttribute((const void*)lstm_persist<128, 8, 512>,
                         cudaFuncAttributeMaxDynamicSharedMemorySize, smem2);

    // ---- pack all weights into bf16 mma fragment order (one-time) ----------
    pack_W<<<(64 * 256 / 2 + 255) / 256, 256>>>(l1Wih, Wih1, 64, 256, 64);
    pack_W<<<(64 * 128 / 2 + 255) / 256, 256>>>(fs1W, Wfs1, 64, 128, 0);
    pack_W<<<(64 * 128 / 2 + 255) / 256, 256>>>(fn1W, Wfn1, 64, 128, 0);
    pack_W<<<(64 * 256 / 2 + 255) / 256, 256>>>(l1Whh, Whh1, 64, 256, 64);
    pack_W<<<(128 * 512 / 2 + 255) / 256, 256>>>(l2Wih, Wih2, 128, 512, 128);
    pack_W<<<(128 * 128 / 2 + 255) / 256, 256>>>(fs2W, Wfs2, 128, 128, 0);
    pack_W<<<(128 * 128 / 2 + 255) / 256, 256>>>(fn2W, Wfn2, 128, 128, 0);
    pack_W<<<(128 * 512 / 2 + 255) / 256, 256>>>(l2Whh, Whh2, 128, 512, 128);

    // P1 = x @ Wih1 + b1  (gate-interleaved, bf16 pairs)
    gemm_tc<<<dim3(NN / 128, 2), 256>>>(
        xn, 64, Wih1, nullptr, 0, nullptr, l1b, nullptr,
        nullptr, Pu1, 256, 0, 64);

    // layer1 LSTM (persistent, tensor cores, 2 CTAs/SM)
    lstm_persist<64, 4, 256><<<NN / 32, 256, smem1>>>(Pu1, Whh1, nbr, HN1);

    // H1 = sigmoid(x@Ws1 + HN1@Wn1 + bs1 + bn1)
    gemm_tc<<<dim3(NN / 128, 1), 256>>>(
        xn, 64, Wfs1, HN1, 64, Wfn1, fs1b, fn1b,
        H1, nullptr, 128, 1, 0);

    // P2 = H1 @ Wih2 + b2  (gate-interleaved, bf16 pairs)
    gemm_tc<<<dim3(NN / 128, 4), 256>>>(
        H1, 128, Wih2, nullptr, 0, nullptr, l2b, nullptr,
        nullptr, Pu2, 512, 0, 128);

    // layer2 LSTM (persistent, tensor cores)
    lstm_persist<128, 8, 512><<<NN / 32, 512, smem2>>>(Pu2, Whh2, nbr, HN2);

    // H2 = sigmoid(H1@Ws2 + HN2@Wn2 + bs2 + bn2)
    gemm_tc<<<dim3(NN / 128, 1), 256>>>(
        H1, 128, Wfs2, HN2, 128, Wfn2, fs2b, fn2b,
        H2, nullptr, 128, 1, 0);

    // readout + head
    readout_kernel<<<1024, 128>>>(H2, rwW, rwb, h1W, h1b, h2W, h2b, out);
}